// round 1
// baseline (speedup 1.0000x reference)
#include <cuda_runtime.h>
#include <cstdint>

typedef unsigned long long u64;

#define BATCH 16
#define CHAN  256
#define H     64
#define W     64
#define MAXD  4
#define PATCH 9
#define ITILE 4   // output rows per block

__device__ __forceinline__ u64 pack2(float lo, float hi) {
    u64 d;
    asm("mov.b64 %0, {%1,%2};" : "=l"(d) : "f"(lo), "f"(hi));
    return d;
}
__device__ __forceinline__ void unpack2(u64 v, float &lo, float &hi) {
    asm("mov.b64 {%0,%1}, %2;" : "=f"(lo), "=f"(hi) : "l"(v));
}
__device__ __forceinline__ void ffma2(u64 &d, u64 a, u64 b) {
    // packed fp32x2 FMA: d.lo += a.lo*b.lo ; d.hi += a.hi*b.hi
    asm("fma.rn.f32x2 %0, %1, %2, %0;" : "+l"(d) : "l"(a), "l"(b));
}

// block: (b, i0) tile of ITILE output rows. 9 warps, warp = di.
// lane = i_local*8 + jseg ; thread owns out[b, di*9 + 0..8, i, j0..j0+7].
__global__ __launch_bounds__(288, 2)
void corr_kernel(const float* __restrict__ x,
                 const float* __restrict__ y,
                 float* __restrict__ out)
{
    const int b    = blockIdx.x >> 4;            // 16 i-tiles per batch
    const int i0   = (blockIdx.x & 15) * ITILE;
    const int di   = threadIdx.x >> 5;           // warp id: 0..8
    const int lane = threadIdx.x & 31;
    const int il   = lane >> 3;
    const int j0   = (lane & 7) * 8;
    const int i    = i0 + il;
    const int yi   = i + di - MAXD;
    const bool rowv = (yi >= 0) && (yi < H);

    const float* xp = x + (((size_t)b * CHAN) * H + i) * W + j0;
    const float* yp = y + (((size_t)b * CHAN) * H + (rowv ? yi : 0)) * W + (j0 - MAXD);

    // y window = q[0..15] = y[.., yi, j0-4 .. j0+11]; 4-float chunks are
    // all-or-nothing valid (j0 multiple of 8):
    const bool cv0 = rowv && (j0 - 4 >= 0);       // chunk 0: cols j0-4..j0-1
    const bool cv1 = rowv;                         // chunk 1: cols j0..j0+3
    const bool cv2 = rowv;                         // chunk 2: cols j0+4..j0+7
    const bool cv3 = rowv && (j0 + 11 < W);        // chunk 3: cols j0+8..j0+11

    u64 acc[4][PATCH];
    #pragma unroll
    for (int t = 0; t < 4; t++)
        #pragma unroll
        for (int dj = 0; dj < PATCH; dj++) acc[t][dj] = 0ull;

    const ulonglong2 Z = make_ulonglong2(0ull, 0ull);

    #pragma unroll 1
    for (int c = 0; c < CHAN; c++) {
        // ---- x: 8 floats, directly as 4 packed pairs (32B aligned) ----
        ulonglong2 xa = *reinterpret_cast<const ulonglong2*>(xp);
        ulonglong2 xb = *reinterpret_cast<const ulonglong2*>(xp + 4);
        u64 xq[4] = { xa.x, xa.y, xb.x, xb.y };

        // ---- y: 16 floats as 8 even pairs Pe[m] = (q[2m], q[2m+1]) ----
        const ulonglong2* yq = reinterpret_cast<const ulonglong2*>(yp); // 16B aligned
        ulonglong2 ya = cv0 ? yq[0] : Z;
        ulonglong2 yb = cv1 ? yq[1] : Z;
        ulonglong2 yc = cv2 ? yq[2] : Z;
        ulonglong2 yd = cv3 ? yq[3] : Z;
        u64 Pe[8] = { ya.x, ya.y, yb.x, yb.y, yc.x, yc.y, yd.x, yd.y };

        // ---- 36 FFMA2: acc[t][dj] += (x[2t],x[2t+1]) * (q[2t+dj], q[2t+dj+1])
        // ordered by pair index k = 2t+dj so odd pairs are short-lived.
        #pragma unroll
        for (int k = 0; k < 15; k++) {
            u64 pr;
            if (k & 1) {
                float e0lo, e0hi, e1lo, e1hi;
                unpack2(Pe[k >> 1], e0lo, e0hi);
                unpack2(Pe[(k >> 1) + 1], e1lo, e1hi);
                pr = pack2(e0hi, e1lo);
            } else {
                pr = Pe[k >> 1];
            }
            #pragma unroll
            for (int t = 0; t < 4; t++) {
                const int dj = k - 2 * t;
                if (dj >= 0 && dj < PATCH) ffma2(acc[t][dj], xq[t], pr);
            }
        }

        xp += H * W;
        yp += H * W;
    }

    // ---- epilogue: scale by 1/C, store 8 contiguous floats per dj ----
    const float inv = 1.0f / (float)CHAN;
    float* op = out + ((((size_t)b * (PATCH * PATCH)) + (size_t)di * PATCH) * H + i) * W + j0;
    #pragma unroll
    for (int dj = 0; dj < PATCH; dj++) {
        float4 v0, v1;
        unpack2(acc[0][dj], v0.x, v0.y);
        unpack2(acc[1][dj], v0.z, v0.w);
        unpack2(acc[2][dj], v1.x, v1.y);
        unpack2(acc[3][dj], v1.z, v1.w);
        v0.x *= inv; v0.y *= inv; v0.z *= inv; v0.w *= inv;
        v1.x *= inv; v1.y *= inv; v1.z *= inv; v1.w *= inv;
        *reinterpret_cast<float4*>(op)     = v0;
        *reinterpret_cast<float4*>(op + 4) = v1;
        op += H * W;
    }
}

extern "C" void kernel_launch(void* const* d_in, const int* in_sizes, int n_in,
                              void* d_out, int out_size)
{
    const float* x = (const float*)d_in[0];
    const float* y = (const float*)d_in[1];
    float* out = (float*)d_out;
    dim3 grid(BATCH * (H / ITILE));   // 256 blocks
    dim3 block(ITILE * 8 * PATCH);    // 288 threads = 9 warps
    corr_kernel<<<grid, block>>>(x, y, out);
}